// round 11
// baseline (speedup 1.0000x reference)
#include <cuda_runtime.h>
#include <math.h>

#define BB 32
#define CC 3
#define HH 512
#define WW 512
#define HW (HH * WW)
#define PI_F 3.14159f

// Heterogeneous grid: groups of 33 blocks = 32 gather blocks + 1 copy block,
// interleaved in dispatch order so the pure-streaming copy co-runs with the
// latency-limited gather blocks and soaks idle DRAM bandwidth.
#define GROUPS 512                      // 512 gather blocks per image * 32 img / 32
#define GRID_X (GROUPS * 33)            // 16896 blocks

// Scratch: per-batch inverse homographies, light params, batch-invariant
// moire field (3 MB, L2-resident, reused 32x).
__device__ float g_minv[BB][9];
__device__ float g_light[3];   // xf, yf, 1/max_len
__device__ float g_moire[CC * HW];

// ---------------------------------------------------------------------------
// Prep: moire field (8 px/thread, 2x float4 stores, fast-math cos) + block-0
// side jobs: closed-form (Heckbert) homography per batch in fp32 and light
// params. Homography is unique up to scale and only used through a
// perspective divide, so the adjugate (un-normalized inverse) suffices.
// ---------------------------------------------------------------------------
__global__ void prep_kernel(const float* __restrict__ theta,
                            const float* __restrict__ center,
                            const float* __restrict__ dst_offsets,
                            const int* __restrict__ light_xy) {
    if (blockIdx.x == 0) {
        int b = threadIdx.x;
        if (b == 32) {
            float xf = (float)light_xy[0];
            float yf = (float)light_xy[1];
            const float S = 512.0f;
            float d0 = sqrtf(xf * xf + yf * yf);
            float d1 = sqrtf((xf - S) * (xf - S) + yf * yf);
            float d2 = sqrtf(xf * xf + (yf - S) * (yf - S));
            float d3 = sqrtf((xf - S) * (xf - S) + (yf - S) * (yf - S));
            float ml = fmaxf(fmaxf(d0, d1), fmaxf(d2, d3)) * 0.5f;
            g_light[0] = xf;
            g_light[1] = yf;
            g_light[2] = 1.0f / ml;
        }
        if (b < BB) {
            const float S = 512.0f;
            // src corners: k=0:(0,0) k=1:(0,S) k=2:(S,0) k=3:(S,S)
            const float sxc[4] = {0.0f, 0.0f, 512.0f, 512.0f};
            const float syc[4] = {0.0f, 512.0f, 0.0f, 512.0f};
            float du[4], dv[4];
            for (int k = 0; k < 4; k++) {
                du[k] = sxc[k] + dst_offsets[(b * 4 + k) * 2 + 0];
                dv[k] = syc[k] + dst_offsets[(b * 4 + k) * 2 + 1];
            }
            // Unit-square param: (0,0)->dst0 (1,0)->dst2 (1,1)->dst3 (0,1)->dst1
            float u0 = du[0], u1 = du[2], u2 = du[3], u3 = du[1];
            float v0 = dv[0], v1 = dv[2], v2 = dv[3], v3 = dv[1];
            float sx = u0 - u1 + u2 - u3;
            float sy = v0 - v1 + v2 - v3;
            float dx1 = u1 - u2, dx2 = u3 - u2;
            float dy1 = v1 - v2, dy2 = v3 - v2;
            float den = dx1 * dy2 - dy1 * dx2;
            float g = (sx * dy2 - sy * dx2) / den;
            float h = (dx1 * sy - dy1 * sx) / den;
            float a = u1 - u0 + g * u1;
            float bq = u3 - u0 + h * u3;
            float c = u0;
            float d = v1 - v0 + g * v1;
            float e = v3 - v0 + h * v3;
            float f = v0;
            float m0 = a,  m1 = bq, m2 = c * S;
            float m3 = d,  m4 = e,  m5 = f * S;
            float m6 = g,  m7 = h,  m8 = S;
            float inv9[9] = {
                m4 * m8 - m5 * m7, m2 * m7 - m1 * m8, m1 * m5 - m2 * m4,
                m5 * m6 - m3 * m8, m0 * m8 - m2 * m6, m2 * m3 - m0 * m5,
                m3 * m7 - m4 * m6, m1 * m6 - m0 * m7, m0 * m4 - m1 * m3};
            float nrm = 1.0f / inv9[8];
            for (int k = 0; k < 9; k++) g_minv[b][k] = inv9[k] * nrm;
        }
    }

    int idx8 = (blockIdx.x * blockDim.x + threadIdx.x) * 8;
    if (idx8 >= CC * HW) return;
    int c = idx8 / HW;
    int rem = idx8 - c * HW;
    int i = rem >> 9;
    int j0 = rem & (WW - 1);   // 8-aligned, all 8 cols in same row

    float cx = center[c * 2 + 0];
    float cy = center[c * 2 + 1];
    float th = theta[c] / 180.0f * PI_F;
    float cth = __cosf(th), sth = __sinf(th);
    float dx = (float)i - cx;
    float dx2 = dx * dx;
    float si = sth * (float)i;

    float m8v[8];
#pragma unroll
    for (int q = 0; q < 8; q++) {
        float jj = (float)(j0 + q);
        float dy = jj - cy;
        float z1 = 0.5f + 0.5f * __cosf(2.0f * PI_F * sqrtf(dx2 + dy * dy));
        float z2 = 0.5f + 0.5f * __cosf(cth * jj + si);
        m8v[q] = fminf(z1, z2) * 2.0f - 1.0f;
    }
    *reinterpret_cast<float4*>(g_moire + idx8) =
        make_float4(m8v[0], m8v[1], m8v[2], m8v[3]);
    *reinterpret_cast<float4*>(g_moire + idx8 + 4) =
        make_float4(m8v[4], m8v[5], m8v[6], m8v[7]);
}

// ---------------------------------------------------------------------------
// Fused heterogeneous kernel. Every 33rd block is a pure cover-copy block
// (float4 streaming at CE-like efficiency); the other 32 do the gather +
// color pipeline (2 px/thread, interior fast path, evict-streaming hints).
// ---------------------------------------------------------------------------
__global__ void __launch_bounds__(256, 8)
main_kernel(const float* __restrict__ imgs,
            const float* __restrict__ noise,
            const float* __restrict__ cover,
            const float* __restrict__ hue_shift,
            const float* __restrict__ bright,
            const float* __restrict__ contrast,
            float* __restrict__ out) {
    const size_t n_img = (size_t)BB * CC * HW;  // 25,165,824 floats

    int bid = blockIdx.x;
    int g = bid / 33;
    int r = bid - g * 33;

    if (r == 32) {
        // ---- Copy block: stream 1/GROUPS of cover into out[n_img..). ----
        const int cnt = (int)(n_img / GROUPS);      // 49152 floats
        const int n4 = cnt / 4;                     // 12288 float4
        const float4* src =
            reinterpret_cast<const float4*>(cover) + (size_t)g * n4;
        float4* dst =
            reinterpret_cast<float4*>(out + n_img) + (size_t)g * n4;
#pragma unroll 4
        for (int k = threadIdx.x; k < n4; k += 256) {
            __stcs(dst + k, __ldcs(src + k));
        }
        return;
    }

    // ---- Gather block ----
    int main_id = g * 32 + r;          // 0 .. 16383
    int b = main_id >> 9;              // image index (512 blocks per image)
    int bx = main_id & 511;
    int p2 = (bx * 256 + threadIdx.x) * 2;   // first pixel of the pair
    int i = p2 >> 9;                   // row (same for both pixels)
    int j0 = p2 & (WW - 1);

    size_t base = (size_t)b * CC * HW + p2;

    // Projective map (row-constant parts hoisted).
    const float* mv = g_minv[b];
    float y = (float)i;
    float cA = mv[1] * y + mv[2];
    float cB = mv[4] * y + mv[5];
    float cW = mv[7] * y + mv[8];

    int ix0[2], iy0[2];
    float wx[2], wy[2];
    bool interior = true;
#pragma unroll
    for (int q = 0; q < 2; q++) {
        float x = (float)(j0 + q);
        float invw = __fdividef(1.0f, mv[6] * x + cW);
        float sxv = (mv[0] * x + cA) * invw;
        float syv = (mv[3] * x + cB) * invw;
        float x0f = floorf(sxv), y0f = floorf(syv);
        wx[q] = sxv - x0f;
        wy[q] = syv - y0f;
        ix0[q] = (int)x0f;
        iy0[q] = (int)y0f;
        interior &= ((unsigned)ix0[q] <= (unsigned)(WW - 2)) &&
                    ((unsigned)iy0[q] <= (unsigned)(HH - 2));
    }

    float ct = contrast[b];
    float br = bright[b];

    const float* imb = imgs + (size_t)b * CC * HW;
    float v[3][2];
    if (interior) {
        // Fast path: all taps in-bounds, raw indices, no masks.
        int o00[2];
#pragma unroll
        for (int q = 0; q < 2; q++) o00[q] = iy0[q] * WW + ix0[q];
#pragma unroll
        for (int c = 0; c < 3; c++) {
            const float* im = imb + c * HW;
            float hs = hue_shift[b * 3 + c];
#pragma unroll
            for (int q = 0; q < 2; q++) {
                float v00 = im[o00[q]];
                float v01 = im[o00[q] + 1];
                float v10 = im[o00[q] + WW];
                float v11 = im[o00[q] + WW + 1];
                float top = v00 + wx[q] * (v01 - v00);
                float bot = v10 + wx[q] * (v11 - v10);
                float val = top + wy[q] * (bot - top);
                float o = val * ct + hs + br;
                v[c][q] = fminf(fmaxf(o, -1.0f), 1.0f);
            }
        }
    } else {
        // Boundary path: kornia zero-padding semantics (mask, clamp).
#pragma unroll
        for (int c = 0; c < 3; c++) {
            const float* im = imb + c * HW;
            float hs = hue_shift[b * 3 + c];
#pragma unroll
            for (int q = 0; q < 2; q++) {
                int x0 = ix0[q], y0 = iy0[q];
                int x1 = x0 + 1, y1 = y0 + 1;
                bool vx0 = (x0 >= 0) && (x0 < WW);
                bool vx1 = (x1 >= 0) && (x1 < WW);
                bool vy0 = (y0 >= 0) && (y0 < HH);
                bool vy1 = (y1 >= 0) && (y1 < HH);
                int cx0 = min(max(x0, 0), WW - 1);
                int cx1 = min(max(x1, 0), WW - 1);
                int cy0 = min(max(y0, 0), HH - 1) * WW;
                int cy1 = min(max(y1, 0), HH - 1) * WW;
                float v00 = (vy0 && vx0) ? im[cy0 + cx0] : 0.0f;
                float v01 = (vy0 && vx1) ? im[cy0 + cx1] : 0.0f;
                float v10 = (vy1 && vx0) ? im[cy1 + cx0] : 0.0f;
                float v11 = (vy1 && vx1) ? im[cy1 + cx1] : 0.0f;
                float val = (1.0f - wy[q]) * ((1.0f - wx[q]) * v00 + wx[q] * v01) +
                            wy[q] * ((1.0f - wx[q]) * v10 + wx[q] * v11);
                float o = val * ct + hs + br;
                v[c][q] = fminf(fmaxf(o, -1.0f), 1.0f);
            }
        }
    }

    // light spot (row-constant di)
    float xf = g_light[0], yf = g_light[1], rml = g_light[2];
    float di = (float)i - xf;
    float di2 = di * di;

    float lum[2], light[2];
#pragma unroll
    for (int q = 0; q < 2; q++) {
        lum[q] = (0.3f * v[0][q] + 0.6f * v[1][q] + 0.1f * v[2][q]) *
                 (1.0f / 3.0f);
        float dj = (float)(j0 + q) - yf;
        float dl = sqrtf(di2 + dj * dj);
        float lw = 1.0f - dl * rml;
        light[q] = (lw > 0.0f) ? lw : 0.0f;
    }

    // Epilogue: streaming loads issued here (coalesced; hidden by occupancy).
    const float kn = 0.031622776601683794f;  // sqrt(0.001)
#pragma unroll
    for (int c = 0; c < 3; c++) {
        size_t off = base + (size_t)c * HW;
        float2 nz = __ldcs(reinterpret_cast<const float2*>(noise + off));
        float2 mo = __ldg(reinterpret_cast<const float2*>(g_moire + c * HW + p2));
        float2 o2;
        o2.x = 0.7f * v[c][0] + 0.3f * lum[0] + light[0] + mo.x * 0.2f +
               kn * nz.x;
        o2.y = 0.7f * v[c][1] + 0.3f * lum[1] + light[1] + mo.y * 0.2f +
               kn * nz.y;
        __stcs(reinterpret_cast<float2*>(out + off), o2);
    }
}

// ---------------------------------------------------------------------------
// Inputs (metadata order): 0 imgs, 1 cover, 2 dst_offsets, 3 hue_shift,
// 4 bright, 5 contrast, 6 light_xy(int32), 7 moire_theta, 8 moire_center,
// 9 noise. Output: [noised | cover], 2 * 32*3*512*512 floats.
// ---------------------------------------------------------------------------
extern "C" void kernel_launch(void* const* d_in, const int* in_sizes, int n_in,
                              void* d_out, int out_size) {
    const float* imgs        = (const float*)d_in[0];
    const float* cover       = (const float*)d_in[1];
    const float* dst_offsets = (const float*)d_in[2];
    const float* hue_shift   = (const float*)d_in[3];
    const float* bright      = (const float*)d_in[4];
    const float* contrast    = (const float*)d_in[5];
    const int*   light_xy    = (const int*)d_in[6];
    const float* moire_theta = (const float*)d_in[7];
    const float* moire_cent  = (const float*)d_in[8];
    const float* noise       = (const float*)d_in[9];
    float* out = (float*)d_out;

    prep_kernel<<<(CC * HW + 2047) / 2048, 256>>>(moire_theta, moire_cent,
                                                  dst_offsets, light_xy);

    main_kernel<<<GRID_X, 256>>>(imgs, noise, cover, hue_shift, bright,
                                 contrast, out);
}

// round 12
// speedup vs baseline: 1.0946x; 1.0946x over previous
#include <cuda_runtime.h>
#include <math.h>

#define BB 32
#define CC 3
#define HH 512
#define WW 512
#define HW (HH * WW)
#define PI_F 3.14159f

#define NMOIRE 384                  // CC*HW / (256*8) moire-writer blocks
#define NGATHER (BB * 512)          // 512 gather blocks per image
#define GRID_X (NMOIRE + NGATHER)

// Scratch: batch-invariant moire field (3 MB, L2-resident, reused 32x) and
// the one-time ready handshake (zero-initialized at module load; across
// graph replays the flag stays set and the moire rewrite is same-value).
__device__ float g_moire[CC * HW];
__device__ int g_done;
__device__ int g_ready;

// ---------------------------------------------------------------------------
// Single fused kernel.
//  blocks [0, NMOIRE):  moire field writers (8 px/thread, 2x float4), then
//                       fence + count; last one sets g_ready.
//  blocks [NMOIRE, ..): gather + color pipeline (R10 config: 2 px/thread,
//                       interior fast path, epilogue streaming with
//                       evict-streaming hints, cover folded). Homography +
//                       light params computed per block by thread 0 into
//                       smem (Heckbert closed form; adjugate inverse is
//                       enough since it feeds a perspective divide).
//                       Moire is only read in the epilogue, behind the
//                       ready-flag spin (wave-1 moire blocks finish first).
// ---------------------------------------------------------------------------
__global__ void __launch_bounds__(256, 8)
fused_kernel(const float* __restrict__ imgs,
             const float* __restrict__ noise,
             const float* __restrict__ cover,
             const float* __restrict__ dst_offsets,
             const float* __restrict__ hue_shift,
             const float* __restrict__ bright,
             const float* __restrict__ contrast,
             const int* __restrict__ light_xy,
             const float* __restrict__ theta,
             const float* __restrict__ center,
             float* __restrict__ out) {
    const size_t n_img = (size_t)BB * CC * HW;

    if (blockIdx.x < NMOIRE) {
        // ---- Moire writer block ----
        int idx8 = (blockIdx.x * 256 + threadIdx.x) * 8;
        int c = idx8 / HW;
        int rem = idx8 - c * HW;
        int i = rem >> 9;
        int j0 = rem & (WW - 1);

        float cx = center[c * 2 + 0];
        float cy = center[c * 2 + 1];
        float th = theta[c] / 180.0f * PI_F;
        float cth = __cosf(th), sth = __sinf(th);
        float dx = (float)i - cx;
        float dx2 = dx * dx;
        float si = sth * (float)i;

#pragma unroll
        for (int h = 0; h < 2; h++) {
            float4 m4v;
            float* mp = &m4v.x;
#pragma unroll
            for (int q = 0; q < 4; q++) {
                float jj = (float)(j0 + h * 4 + q);
                float dy = jj - cy;
                float z1 = 0.5f + 0.5f * __cosf(2.0f * PI_F * sqrtf(dx2 + dy * dy));
                float z2 = 0.5f + 0.5f * __cosf(cth * jj + si);
                mp[q] = fminf(z1, z2) * 2.0f - 1.0f;
            }
            *reinterpret_cast<float4*>(g_moire + idx8 + h * 4) = m4v;
        }

        __threadfence();      // make this thread's moire stores visible
        __syncthreads();      // whole block done
        if (threadIdx.x == 0) {
            if (atomicAdd(&g_done, 1) == NMOIRE - 1) {
                __threadfence();
                g_ready = 1;  // release: all moire data visible before flag
                __threadfence();
            }
        }
        return;
    }

    // ---- Gather block ----
    int main_id = blockIdx.x - NMOIRE;
    int b = main_id >> 9;              // image index (512 blocks per image)
    int bx = main_id & 511;
    int p2 = (bx * 256 + threadIdx.x) * 2;
    int i = p2 >> 9;                   // row (same for both pixels)
    int j0 = p2 & (WW - 1);

    size_t base = (size_t)b * CC * HW + p2;

    // Thread 0: closed-form homography (adjugate inverse) + light params.
    __shared__ float sM[12];
    if (threadIdx.x == 0) {
        const float S = 512.0f;
        // src corners: k=0:(0,0) k=1:(0,S) k=2:(S,0) k=3:(S,S)
        const float sxc[4] = {0.0f, 0.0f, 512.0f, 512.0f};
        const float syc[4] = {0.0f, 512.0f, 0.0f, 512.0f};
        float du[4], dv[4];
        for (int k = 0; k < 4; k++) {
            du[k] = sxc[k] + dst_offsets[(b * 4 + k) * 2 + 0];
            dv[k] = syc[k] + dst_offsets[(b * 4 + k) * 2 + 1];
        }
        // Unit-square param: (0,0)->dst0 (1,0)->dst2 (1,1)->dst3 (0,1)->dst1
        float u0 = du[0], u1 = du[2], u2 = du[3], u3 = du[1];
        float v0 = dv[0], v1 = dv[2], v2 = dv[3], v3 = dv[1];
        float sx = u0 - u1 + u2 - u3;
        float sy = v0 - v1 + v2 - v3;
        float dx1 = u1 - u2, dx2 = u3 - u2;
        float dy1 = v1 - v2, dy2 = v3 - v2;
        float den = dx1 * dy2 - dy1 * dx2;
        float g = (sx * dy2 - sy * dx2) / den;
        float h = (dx1 * sy - dy1 * sx) / den;
        float a = u1 - u0 + g * u1;
        float bq = u3 - u0 + h * u3;
        float cc = u0;
        float d = v1 - v0 + g * v1;
        float e = v3 - v0 + h * v3;
        float f = v0;
        float m0 = a,  m1 = bq, m2 = cc * S;
        float m3 = d,  m4 = e,  m5 = f * S;
        float m6 = g,  m7 = h,  m8 = S;
        float inv9[9] = {
            m4 * m8 - m5 * m7, m2 * m7 - m1 * m8, m1 * m5 - m2 * m4,
            m5 * m6 - m3 * m8, m0 * m8 - m2 * m6, m2 * m3 - m0 * m5,
            m3 * m7 - m4 * m6, m1 * m6 - m0 * m7, m0 * m4 - m1 * m3};
        float nrm = 1.0f / inv9[8];
        for (int k = 0; k < 9; k++) sM[k] = inv9[k] * nrm;

        float xf = (float)light_xy[0];
        float yf = (float)light_xy[1];
        float d0 = sqrtf(xf * xf + yf * yf);
        float d1 = sqrtf((xf - S) * (xf - S) + yf * yf);
        float d2 = sqrtf(xf * xf + (yf - S) * (yf - S));
        float d3 = sqrtf((xf - S) * (xf - S) + (yf - S) * (yf - S));
        float ml = fmaxf(fmaxf(d0, d1), fmaxf(d2, d3)) * 0.5f;
        sM[9] = xf;
        sM[10] = yf;
        sM[11] = 1.0f / ml;
    }
    __syncthreads();

    // Projective map (row-constant parts hoisted).
    float y = (float)i;
    float cA = sM[1] * y + sM[2];
    float cB = sM[4] * y + sM[5];
    float cW = sM[7] * y + sM[8];

    int ix0[2], iy0[2];
    float wx[2], wy[2];
    bool interior = true;
#pragma unroll
    for (int q = 0; q < 2; q++) {
        float x = (float)(j0 + q);
        float invw = __fdividef(1.0f, sM[6] * x + cW);
        float sxv = (sM[0] * x + cA) * invw;
        float syv = (sM[3] * x + cB) * invw;
        float x0f = floorf(sxv), y0f = floorf(syv);
        wx[q] = sxv - x0f;
        wy[q] = syv - y0f;
        ix0[q] = (int)x0f;
        iy0[q] = (int)y0f;
        interior &= ((unsigned)ix0[q] <= (unsigned)(WW - 2)) &&
                    ((unsigned)iy0[q] <= (unsigned)(HH - 2));
    }

    float ct = contrast[b];
    float br = bright[b];

    const float* imb = imgs + (size_t)b * CC * HW;
    float v[3][2];
    if (interior) {
        // Fast path: all taps in-bounds, raw indices, no masks.
        int o00[2];
#pragma unroll
        for (int q = 0; q < 2; q++) o00[q] = iy0[q] * WW + ix0[q];
#pragma unroll
        for (int c = 0; c < 3; c++) {
            const float* im = imb + c * HW;
            float hs = hue_shift[b * 3 + c];
#pragma unroll
            for (int q = 0; q < 2; q++) {
                float v00 = im[o00[q]];
                float v01 = im[o00[q] + 1];
                float v10 = im[o00[q] + WW];
                float v11 = im[o00[q] + WW + 1];
                float top = v00 + wx[q] * (v01 - v00);
                float bot = v10 + wx[q] * (v11 - v10);
                float val = top + wy[q] * (bot - top);
                float o = val * ct + hs + br;
                v[c][q] = fminf(fmaxf(o, -1.0f), 1.0f);
            }
        }
    } else {
        // Boundary path: kornia zero-padding semantics (mask, clamp).
#pragma unroll
        for (int c = 0; c < 3; c++) {
            const float* im = imb + c * HW;
            float hs = hue_shift[b * 3 + c];
#pragma unroll
            for (int q = 0; q < 2; q++) {
                int x0 = ix0[q], y0 = iy0[q];
                int x1 = x0 + 1, y1 = y0 + 1;
                bool vx0 = (x0 >= 0) && (x0 < WW);
                bool vx1 = (x1 >= 0) && (x1 < WW);
                bool vy0 = (y0 >= 0) && (y0 < HH);
                bool vy1 = (y1 >= 0) && (y1 < HH);
                int cx0 = min(max(x0, 0), WW - 1);
                int cx1 = min(max(x1, 0), WW - 1);
                int cy0 = min(max(y0, 0), HH - 1) * WW;
                int cy1 = min(max(y1, 0), HH - 1) * WW;
                float v00 = (vy0 && vx0) ? im[cy0 + cx0] : 0.0f;
                float v01 = (vy0 && vx1) ? im[cy0 + cx1] : 0.0f;
                float v10 = (vy1 && vx0) ? im[cy1 + cx0] : 0.0f;
                float v11 = (vy1 && vx1) ? im[cy1 + cx1] : 0.0f;
                float val = (1.0f - wy[q]) * ((1.0f - wx[q]) * v00 + wx[q] * v01) +
                            wy[q] * ((1.0f - wx[q]) * v10 + wx[q] * v11);
                float o = val * ct + hs + br;
                v[c][q] = fminf(fmaxf(o, -1.0f), 1.0f);
            }
        }
    }

    // light spot (row-constant di)
    float xf = sM[9], yf = sM[10], rml = sM[11];
    float di = (float)i - xf;
    float di2 = di * di;

    float lum[2], light[2];
#pragma unroll
    for (int q = 0; q < 2; q++) {
        lum[q] = (0.3f * v[0][q] + 0.6f * v[1][q] + 0.1f * v[2][q]) *
                 (1.0f / 3.0f);
        float dj = (float)(j0 + q) - yf;
        float dl = sqrtf(di2 + dj * dj);
        float lw = 1.0f - dl * rml;
        light[q] = (lw > 0.0f) ? lw : 0.0f;
    }

    // Wait for the moire field (wave-1 moire blocks finish in a few us;
    // on graph replays the flag is already set — zero cost).
    if (threadIdx.x == 0) {
        while (((volatile int*)&g_ready)[0] == 0) __nanosleep(64);
    }
    __syncthreads();
    __threadfence();  // acquire: order moire reads after the flag

    // Epilogue: streaming loads (coalesced; evict-streaming, no L2 reuse).
    const float kn = 0.031622776601683794f;  // sqrt(0.001)
#pragma unroll
    for (int c = 0; c < 3; c++) {
        size_t off = base + (size_t)c * HW;
        float2 nz = __ldcs(reinterpret_cast<const float2*>(noise + off));
        float2 cv = __ldcs(reinterpret_cast<const float2*>(cover + off));
        float2 mo = *reinterpret_cast<const float2*>(g_moire + c * HW + p2);
        float2 o2;
        o2.x = 0.7f * v[c][0] + 0.3f * lum[0] + light[0] + mo.x * 0.2f +
               kn * nz.x;
        o2.y = 0.7f * v[c][1] + 0.3f * lum[1] + light[1] + mo.y * 0.2f +
               kn * nz.y;
        __stcs(reinterpret_cast<float2*>(out + off), o2);
        __stcs(reinterpret_cast<float2*>(out + n_img + off), cv);
    }
}

// ---------------------------------------------------------------------------
// Inputs (metadata order): 0 imgs, 1 cover, 2 dst_offsets, 3 hue_shift,
// 4 bright, 5 contrast, 6 light_xy(int32), 7 moire_theta, 8 moire_center,
// 9 noise. Output: [noised | cover], 2 * 32*3*512*512 floats.
// ---------------------------------------------------------------------------
extern "C" void kernel_launch(void* const* d_in, const int* in_sizes, int n_in,
                              void* d_out, int out_size) {
    const float* imgs        = (const float*)d_in[0];
    const float* cover       = (const float*)d_in[1];
    const float* dst_offsets = (const float*)d_in[2];
    const float* hue_shift   = (const float*)d_in[3];
    const float* bright      = (const float*)d_in[4];
    const float* contrast    = (const float*)d_in[5];
    const int*   light_xy    = (const int*)d_in[6];
    const float* moire_theta = (const float*)d_in[7];
    const float* moire_cent  = (const float*)d_in[8];
    const float* noise       = (const float*)d_in[9];
    float* out = (float*)d_out;

    fused_kernel<<<GRID_X, 256>>>(imgs, noise, cover, dst_offsets, hue_shift,
                                  bright, contrast, light_xy, moire_theta,
                                  moire_cent, out);
}

// round 13
// speedup vs baseline: 1.2122x; 1.1074x over previous
#include <cuda_runtime.h>
#include <math.h>

#define BB 32
#define CC 3
#define HH 512
#define WW 512
#define HW (HH * WW)
#define PI_F 3.14159f

#define NMOIRE 384                  // CC*HW / (256*8) moire blocks
#define NGATHER (BB * 512)          // 512 gather blocks per image

// Batch-invariant moire field (3 MB, L2-resident, reused 32x).
__device__ float g_moire[CC * HW];

// ---------------------------------------------------------------------------
// Prep (primary kernel): moire field only. 8 px/thread, 2x float4 stores,
// fast-math cos. Each block triggers the dependent launch when done — the
// main kernel starts concurrently and only syncs on this data at its
// epilogue via cudaGridDependencySynchronize().
// ---------------------------------------------------------------------------
__global__ void __launch_bounds__(256)
prep_kernel(const float* __restrict__ theta,
            const float* __restrict__ center) {
    int idx8 = (blockIdx.x * 256 + threadIdx.x) * 8;
    int c = idx8 / HW;
    int rem = idx8 - c * HW;
    int i = rem >> 9;
    int j0 = rem & (WW - 1);   // 8-aligned, all 8 cols in same row

    float cx = center[c * 2 + 0];
    float cy = center[c * 2 + 1];
    float th = theta[c] / 180.0f * PI_F;
    float cth = __cosf(th), sth = __sinf(th);
    float dx = (float)i - cx;
    float dx2 = dx * dx;
    float si = sth * (float)i;

#pragma unroll
    for (int h = 0; h < 2; h++) {
        float4 m4v;
        float* mp = &m4v.x;
#pragma unroll
        for (int q = 0; q < 4; q++) {
            float jj = (float)(j0 + h * 4 + q);
            float dy = jj - cy;
            float z1 = 0.5f + 0.5f * __cosf(2.0f * PI_F * sqrtf(dx2 + dy * dy));
            float z2 = 0.5f + 0.5f * __cosf(cth * jj + si);
            mp[q] = fminf(z1, z2) * 2.0f - 1.0f;
        }
        *reinterpret_cast<float4*>(g_moire + idx8 + h * 4) = m4v;
    }

#if __CUDA_ARCH__ >= 900
    cudaTriggerProgrammaticLaunchCompletion();
#endif
}

// ---------------------------------------------------------------------------
// Main (dependent kernel): gather + color pipeline (R10 config: 2 px/thread,
// interior fast path, epilogue streaming loads with evict-streaming hints,
// cover folded). Homography + light params computed per block by thread 0
// into smem (Heckbert closed form; adjugate inverse suffices since it feeds
// a perspective divide). Moire is consumed only after
// cudaGridDependencySynchronize() — no manual fences, no L1 flush.
// ---------------------------------------------------------------------------
__global__ void __launch_bounds__(256, 8)
main_kernel(const float* __restrict__ imgs,
            const float* __restrict__ noise,
            const float* __restrict__ cover,
            const float* __restrict__ dst_offsets,
            const float* __restrict__ hue_shift,
            const float* __restrict__ bright,
            const float* __restrict__ contrast,
            const int* __restrict__ light_xy,
            float* __restrict__ out) {
    const size_t n_img = (size_t)BB * CC * HW;

    int main_id = blockIdx.x;
    int b = main_id >> 9;              // image index (512 blocks per image)
    int bx = main_id & 511;
    int p2 = (bx * 256 + threadIdx.x) * 2;
    int i = p2 >> 9;                   // row (same for both pixels)
    int j0 = p2 & (WW - 1);

    size_t base = (size_t)b * CC * HW + p2;

    // Thread 0: closed-form homography (adjugate inverse) + light params.
    __shared__ float sM[12];
    if (threadIdx.x == 0) {
        const float S = 512.0f;
        // src corners: k=0:(0,0) k=1:(0,S) k=2:(S,0) k=3:(S,S)
        const float sxc[4] = {0.0f, 0.0f, 512.0f, 512.0f};
        const float syc[4] = {0.0f, 512.0f, 0.0f, 512.0f};
        float du[4], dv[4];
        for (int k = 0; k < 4; k++) {
            du[k] = sxc[k] + dst_offsets[(b * 4 + k) * 2 + 0];
            dv[k] = syc[k] + dst_offsets[(b * 4 + k) * 2 + 1];
        }
        // Unit-square param: (0,0)->dst0 (1,0)->dst2 (1,1)->dst3 (0,1)->dst1
        float u0 = du[0], u1 = du[2], u2 = du[3], u3 = du[1];
        float v0 = dv[0], v1 = dv[2], v2 = dv[3], v3 = dv[1];
        float sx = u0 - u1 + u2 - u3;
        float sy = v0 - v1 + v2 - v3;
        float dx1 = u1 - u2, dx2 = u3 - u2;
        float dy1 = v1 - v2, dy2 = v3 - v2;
        float den = dx1 * dy2 - dy1 * dx2;
        float g = (sx * dy2 - sy * dx2) / den;
        float h = (dx1 * sy - dy1 * sx) / den;
        float a = u1 - u0 + g * u1;
        float bq = u3 - u0 + h * u3;
        float cc = u0;
        float d = v1 - v0 + g * v1;
        float e = v3 - v0 + h * v3;
        float f = v0;
        float m0 = a,  m1 = bq, m2 = cc * S;
        float m3 = d,  m4 = e,  m5 = f * S;
        float m6 = g,  m7 = h,  m8 = S;
        float inv9[9] = {
            m4 * m8 - m5 * m7, m2 * m7 - m1 * m8, m1 * m5 - m2 * m4,
            m5 * m6 - m3 * m8, m0 * m8 - m2 * m6, m2 * m3 - m0 * m5,
            m3 * m7 - m4 * m6, m1 * m6 - m0 * m7, m0 * m4 - m1 * m3};
        float nrm = 1.0f / inv9[8];
        for (int k = 0; k < 9; k++) sM[k] = inv9[k] * nrm;

        float xf = (float)light_xy[0];
        float yf = (float)light_xy[1];
        float d0 = sqrtf(xf * xf + yf * yf);
        float d1 = sqrtf((xf - S) * (xf - S) + yf * yf);
        float d2 = sqrtf(xf * xf + (yf - S) * (yf - S));
        float d3 = sqrtf((xf - S) * (xf - S) + (yf - S) * (yf - S));
        float ml = fmaxf(fmaxf(d0, d1), fmaxf(d2, d3)) * 0.5f;
        sM[9] = xf;
        sM[10] = yf;
        sM[11] = 1.0f / ml;
    }
    __syncthreads();

    // Projective map (row-constant parts hoisted).
    float y = (float)i;
    float cA = sM[1] * y + sM[2];
    float cB = sM[4] * y + sM[5];
    float cW = sM[7] * y + sM[8];

    int ix0[2], iy0[2];
    float wx[2], wy[2];
    bool interior = true;
#pragma unroll
    for (int q = 0; q < 2; q++) {
        float x = (float)(j0 + q);
        float invw = __fdividef(1.0f, sM[6] * x + cW);
        float sxv = (sM[0] * x + cA) * invw;
        float syv = (sM[3] * x + cB) * invw;
        float x0f = floorf(sxv), y0f = floorf(syv);
        wx[q] = sxv - x0f;
        wy[q] = syv - y0f;
        ix0[q] = (int)x0f;
        iy0[q] = (int)y0f;
        interior &= ((unsigned)ix0[q] <= (unsigned)(WW - 2)) &&
                    ((unsigned)iy0[q] <= (unsigned)(HH - 2));
    }

    float ct = contrast[b];
    float br = bright[b];

    const float* imb = imgs + (size_t)b * CC * HW;
    float v[3][2];
    if (interior) {
        // Fast path: all taps in-bounds, raw indices, no masks.
        int o00[2];
#pragma unroll
        for (int q = 0; q < 2; q++) o00[q] = iy0[q] * WW + ix0[q];
#pragma unroll
        for (int c = 0; c < 3; c++) {
            const float* im = imb + c * HW;
            float hs = hue_shift[b * 3 + c];
#pragma unroll
            for (int q = 0; q < 2; q++) {
                float v00 = im[o00[q]];
                float v01 = im[o00[q] + 1];
                float v10 = im[o00[q] + WW];
                float v11 = im[o00[q] + WW + 1];
                float top = v00 + wx[q] * (v01 - v00);
                float bot = v10 + wx[q] * (v11 - v10);
                float val = top + wy[q] * (bot - top);
                float o = val * ct + hs + br;
                v[c][q] = fminf(fmaxf(o, -1.0f), 1.0f);
            }
        }
    } else {
        // Boundary path: kornia zero-padding semantics (mask, clamp).
#pragma unroll
        for (int c = 0; c < 3; c++) {
            const float* im = imb + c * HW;
            float hs = hue_shift[b * 3 + c];
#pragma unroll
            for (int q = 0; q < 2; q++) {
                int x0 = ix0[q], y0 = iy0[q];
                int x1 = x0 + 1, y1 = y0 + 1;
                bool vx0 = (x0 >= 0) && (x0 < WW);
                bool vx1 = (x1 >= 0) && (x1 < WW);
                bool vy0 = (y0 >= 0) && (y0 < HH);
                bool vy1 = (y1 >= 0) && (y1 < HH);
                int cx0 = min(max(x0, 0), WW - 1);
                int cx1 = min(max(x1, 0), WW - 1);
                int cy0 = min(max(y0, 0), HH - 1) * WW;
                int cy1 = min(max(y1, 0), HH - 1) * WW;
                float v00 = (vy0 && vx0) ? im[cy0 + cx0] : 0.0f;
                float v01 = (vy0 && vx1) ? im[cy0 + cx1] : 0.0f;
                float v10 = (vy1 && vx0) ? im[cy1 + cx0] : 0.0f;
                float v11 = (vy1 && vx1) ? im[cy1 + cx1] : 0.0f;
                float val = (1.0f - wy[q]) * ((1.0f - wx[q]) * v00 + wx[q] * v01) +
                            wy[q] * ((1.0f - wx[q]) * v10 + wx[q] * v11);
                float o = val * ct + hs + br;
                v[c][q] = fminf(fmaxf(o, -1.0f), 1.0f);
            }
        }
    }

    // light spot (row-constant di)
    float xf = sM[9], yf = sM[10], rml = sM[11];
    float di = (float)i - xf;
    float di2 = di * di;

    float lum[2], light[2];
#pragma unroll
    for (int q = 0; q < 2; q++) {
        lum[q] = (0.3f * v[0][q] + 0.6f * v[1][q] + 0.1f * v[2][q]) *
                 (1.0f / 3.0f);
        float dj = (float)(j0 + q) - yf;
        float dl = sqrtf(di2 + dj * dj);
        float lw = 1.0f - dl * rml;
        light[q] = (lw > 0.0f) ? lw : 0.0f;
    }

    // Moire is produced by the primary (prep) kernel; PDL sync gives the
    // visibility guarantee without any manual fence / L1 flush.
#if __CUDA_ARCH__ >= 900
    cudaGridDependencySynchronize();
#endif

    // Epilogue: streaming loads (coalesced; evict-streaming, no L2 reuse).
    const float kn = 0.031622776601683794f;  // sqrt(0.001)
#pragma unroll
    for (int c = 0; c < 3; c++) {
        size_t off = base + (size_t)c * HW;
        float2 nz = __ldcs(reinterpret_cast<const float2*>(noise + off));
        float2 cv = __ldcs(reinterpret_cast<const float2*>(cover + off));
        float2 mo = __ldg(reinterpret_cast<const float2*>(g_moire + c * HW + p2));
        float2 o2;
        o2.x = 0.7f * v[c][0] + 0.3f * lum[0] + light[0] + mo.x * 0.2f +
               kn * nz.x;
        o2.y = 0.7f * v[c][1] + 0.3f * lum[1] + light[1] + mo.y * 0.2f +
               kn * nz.y;
        __stcs(reinterpret_cast<float2*>(out + off), o2);
        __stcs(reinterpret_cast<float2*>(out + n_img + off), cv);
    }
}

// ---------------------------------------------------------------------------
// Inputs (metadata order): 0 imgs, 1 cover, 2 dst_offsets, 3 hue_shift,
// 4 bright, 5 contrast, 6 light_xy(int32), 7 moire_theta, 8 moire_center,
// 9 noise. Output: [noised | cover], 2 * 32*3*512*512 floats.
//
// prep is the PDL primary; main is launched with programmatic stream
// serialization allowed so it overlaps prep and only serializes at the
// cudaGridDependencySynchronize() in its epilogue.
// ---------------------------------------------------------------------------
extern "C" void kernel_launch(void* const* d_in, const int* in_sizes, int n_in,
                              void* d_out, int out_size) {
    const float* imgs        = (const float*)d_in[0];
    const float* cover       = (const float*)d_in[1];
    const float* dst_offsets = (const float*)d_in[2];
    const float* hue_shift   = (const float*)d_in[3];
    const float* bright      = (const float*)d_in[4];
    const float* contrast    = (const float*)d_in[5];
    const int*   light_xy    = (const int*)d_in[6];
    const float* moire_theta = (const float*)d_in[7];
    const float* moire_cent  = (const float*)d_in[8];
    const float* noise       = (const float*)d_in[9];
    float* out = (float*)d_out;

    prep_kernel<<<NMOIRE, 256>>>(moire_theta, moire_cent);

    cudaLaunchConfig_t cfg = {};
    cfg.gridDim = dim3(NGATHER, 1, 1);
    cfg.blockDim = dim3(256, 1, 1);
    cfg.dynamicSmemBytes = 0;
    cfg.stream = 0;
    cudaLaunchAttribute attrs[1];
    attrs[0].id = cudaLaunchAttributeProgrammaticStreamSerialization;
    attrs[0].val.programmaticStreamSerializationAllowed = 1;
    cfg.attrs = attrs;
    cfg.numAttrs = 1;

    cudaError_t err = cudaLaunchKernelEx(&cfg, main_kernel,
                                         imgs, noise, cover, dst_offsets,
                                         hue_shift, bright, contrast,
                                         light_xy, out);
    if (err != cudaSuccess) {
        // Fallback: plain serialized launch (correctness preserved).
        main_kernel<<<NGATHER, 256>>>(imgs, noise, cover, dst_offsets,
                                      hue_shift, bright, contrast,
                                      light_xy, out);
    }
}